// round 15
// baseline (speedup 1.0000x reference)
#include <cuda_runtime.h>
#include <cuda_bf16.h>
#include <cstdint>

#define N_NODES 50000
#define N_EDGES 800000
#define DIM 128

// ---------------- device scratch (no allocations allowed) ----------------
__device__ int   g_count[N_NODES];
__device__ int   g_rowptr[N_NODES + 1];
__device__ int   g_esrc[N_EDGES];
__device__ int   g_bsum[256];
__device__ int   g_boff[256];
__device__ float g_agg[N_NODES * DIM];
__device__ float g_h1[N_NODES * DIM];
__device__ float g_h2[N_NODES * DIM];
__device__ float g_wt0[256 * 128];     // tf32-rounded [Wself0;Wneigh0]
__device__ float g_wt1[256 * 128];
__device__ float g_wt2[256 * 64];

__device__ __forceinline__ uint32_t f2tf32(float f) {
    uint32_t u;
    asm("cvt.rna.tf32.f32 %0, %1;" : "=r"(u) : "f"(f));
    return u;
}

#define MMA_TF32(c, a, b0, b1)                                               \
    asm volatile("mma.sync.aligned.m16n8k8.row.col.f32.tf32.tf32.f32 "       \
        "{%0,%1,%2,%3}, {%4,%5,%6,%7}, {%8,%9}, {%0,%1,%2,%3};"              \
        : "+f"((c)[0]), "+f"((c)[1]), "+f"((c)[2]), "+f"((c)[3])             \
        : "r"((a)[0]), "r"((a)[1]), "r"((a)[2]), "r"((a)[3]),                \
          "r"(b0), "r"(b1))

// ---------------- prep: zero counts + block sums + tf32 weights ----------------
__global__ void prep_kernel(const float* __restrict__ Ws0, const float* __restrict__ Wn0,
                            const float* __restrict__ Ws1, const float* __restrict__ Wn1,
                            const float* __restrict__ Ws2, const float* __restrict__ Wn2) {
    int i = blockIdx.x * blockDim.x + threadIdx.x;
    if (i < N_NODES) g_count[i] = 0;
    if (i < 256) g_bsum[i] = 0;
    if (i < 256 * 128) {
        int k = i / 128, o = i % 128;
        float v0 = (k < 128) ? Ws0[k * 128 + o] : Wn0[(k - 128) * 128 + o];
        float v1 = (k < 128) ? Ws1[k * 128 + o] : Wn1[(k - 128) * 128 + o];
        g_wt0[i] = __uint_as_float(f2tf32(v0));
        g_wt1[i] = __uint_as_float(f2tf32(v1));
    }
    if (i < 256 * 64) {
        int k = i / 64, o = i % 64;
        float v2 = (k < 128) ? Ws2[k * 64 + o] : Wn2[(k - 128) * 64 + o];
        g_wt2[i] = __uint_as_float(f2tf32(v2));
    }
}

// ---------------- CSR build ----------------
// hist also accumulates per-256-node-chunk sums (replaces reduce_counts_kernel)
__global__ void hist_kernel(const int* __restrict__ dst) {
    int e = blockIdx.x * blockDim.x + threadIdx.x;
    if (e < N_EDGES) {
        unsigned d = (unsigned)dst[e];
        if (d < N_NODES) {
            atomicAdd(&g_count[d], 1);
            atomicAdd(&g_bsum[d >> 8], 1);
        }
    }
}

__device__ __forceinline__ int block_incl_scan256(int v, int* wsum) {
    int lane = threadIdx.x & 31, w = threadIdx.x >> 5;
    int s = v;
#pragma unroll
    for (int off = 1; off < 32; off <<= 1) {
        int x = __shfl_up_sync(0xFFFFFFFFu, s, off);
        if (lane >= off) s += x;
    }
    if (lane == 31) wsum[w] = s;
    __syncthreads();
    if (w == 0) {
        int ws = (lane < 8) ? wsum[lane] : 0;
#pragma unroll
        for (int off = 1; off < 8; off <<= 1) {
            int x = __shfl_up_sync(0xFFFFFFFFu, ws, off);
            if (lane >= off) ws += x;
        }
        if (lane < 8) wsum[lane] = ws;
    }
    __syncthreads();
    return s + ((w > 0) ? wsum[w - 1] : 0);
}

__global__ void scan_partials_kernel() {       // 1 x 256: scan g_bsum -> g_boff
    __shared__ int wsum[8];
    int t = threadIdx.x;
    int v = (t < 196) ? g_bsum[t] : 0;
    int incl = block_incl_scan256(v, wsum);
    if (t < 196) g_boff[t] = incl - v;
}

__global__ void block_scan_kernel() {          // 196 x 256; writes rowptr + cursor
    __shared__ int wsum[8];
    int i = blockIdx.x * 256 + threadIdx.x;
    int v = (i < N_NODES) ? g_count[i] : 0;
    int incl = block_incl_scan256(v, wsum);
    if (i < N_NODES) {
        int excl = g_boff[blockIdx.x] + incl - v;
        g_rowptr[i + 1] = excl + v;
        g_count[i] = excl;
    }
    if (i == 0) g_rowptr[0] = 0;
}

__global__ void scatter_kernel(const int* __restrict__ src, const int* __restrict__ dst) {
    int e = blockIdx.x * blockDim.x + threadIdx.x;
    if (e < N_EDGES) {
        unsigned d = (unsigned)dst[e];
        unsigned s = (unsigned)src[e];
        if (d < N_NODES && s < N_NODES) {
            int pos = atomicAdd(&g_count[d], 1);
            if ((unsigned)pos < N_EDGES) g_esrc[pos] = (int)s;
        }
    }
}

// ---------------- mean aggregation: one warp per node, unrolled x4 for MLP ----
template <int HSEL>
__global__ void aggregate_kernel(const float* __restrict__ hext) {
    const float* __restrict__ h =
        (HSEL == 0) ? hext : ((HSEL == 1) ? (const float*)g_h1 : (const float*)g_h2);
    int warp = (blockIdx.x * blockDim.x + threadIdx.x) >> 5;
    int lane = threadIdx.x & 31;
    if (warp >= N_NODES) return;
    int beg = g_rowptr[warp];
    int end = g_rowptr[warp + 1];
    float ax = 0.f, ay = 0.f, az = 0.f, aw = 0.f;
    int i = beg;
    for (; i + 3 < end; i += 4) {
        int s0 = g_esrc[i + 0];
        int s1 = g_esrc[i + 1];
        int s2 = g_esrc[i + 2];
        int s3 = g_esrc[i + 3];
        float4 v0 = *reinterpret_cast<const float4*>(&h[(size_t)s0 * DIM + lane * 4]);
        float4 v1 = *reinterpret_cast<const float4*>(&h[(size_t)s1 * DIM + lane * 4]);
        float4 v2 = *reinterpret_cast<const float4*>(&h[(size_t)s2 * DIM + lane * 4]);
        float4 v3 = *reinterpret_cast<const float4*>(&h[(size_t)s3 * DIM + lane * 4]);
        ax += (v0.x + v1.x) + (v2.x + v3.x);
        ay += (v0.y + v1.y) + (v2.y + v3.y);
        az += (v0.z + v1.z) + (v2.z + v3.z);
        aw += (v0.w + v1.w) + (v2.w + v3.w);
    }
    for (; i < end; i++) {
        int s = g_esrc[i];
        float4 v = *reinterpret_cast<const float4*>(&h[(size_t)s * DIM + lane * 4]);
        ax += v.x; ay += v.y; az += v.z; aw += v.w;
    }
    float inv = (end > beg) ? (1.0f / (float)(end - beg)) : 0.0f;
    float4 r; r.x = ax * inv; r.y = ay * inv; r.z = az * inv; r.w = aw * inv;
    *reinterpret_cast<float4*>(&g_agg[(size_t)warp * DIM + lane * 4]) = r;
}

// ---------------- fused GEMM (tf32 mma): full K=256, A = [hin | g_agg] ----------------
// Block: 256 threads (8 warps), tile 128 nodes x OUT, warp grid 4Mx2N, m16n8k8.
template <int OUT, bool RELU, int HSEL, int DSEL, int WSEL>
__global__ __launch_bounds__(256)
void gemm_tc_kernel(const float* __restrict__ hinext,
                    const float* __restrict__ bias, float* __restrict__ outext) {
    const float* __restrict__ hin =
        (HSEL == 0) ? hinext : ((HSEL == 1) ? (const float*)g_h1 : (const float*)g_h2);
    float* __restrict__ out =
        (DSEL == 0) ? outext : ((DSEL == 1) ? (float*)g_h1 : (float*)g_h2);
    const float* __restrict__ Wt =
        (WSEL == 0) ? g_wt0 : (WSEL == 1) ? g_wt1 : g_wt2;

    constexpr int AP = 36;
    constexpr int BP = OUT + 8;
    constexpr int NS = OUT / 16;

    extern __shared__ float smem[];
    float* As = smem;                  // [128][AP]
    float* Bs = smem + 128 * AP;       // [32][BP]
    float* bs = Bs + 32 * BP;          // [OUT]

    const int tid   = threadIdx.x;
    const int lane  = tid & 31;
    const int wid   = tid >> 5;
    const int g     = lane >> 2;
    const int t4    = lane & 3;
    const int warpM = wid & 3;
    const int warpN = wid >> 2;
    const int node0 = blockIdx.x * 128;

    if (tid < OUT) bs[tid] = bias[tid];

    float acc[2][NS][4];
#pragma unroll
    for (int ms = 0; ms < 2; ms++)
#pragma unroll
        for (int ns = 0; ns < NS; ns++)
#pragma unroll
            for (int c = 0; c < 4; c++) acc[ms][ns][c] = 0.f;

    for (int kt = 0; kt < 8; kt++) {
        const int k0 = kt * 32;
        // ---- stage A: [hin | g_agg] ----
        {
            const float* srcb = (k0 < 128) ? hin : (const float*)g_agg;
            const int koff = (k0 < 128) ? k0 : (k0 - 128);
            const float4 z4 = make_float4(0.f, 0.f, 0.f, 0.f);
#pragma unroll
            for (int i = tid; i < 1024; i += 256) {
                int j  = i >> 3;
                int k4 = i & 7;
                int n  = node0 + j;
                float4 v = (n < N_NODES)
                    ? *reinterpret_cast<const float4*>(&srcb[(size_t)n * DIM + koff + k4 * 4])
                    : z4;
                float* d = &As[j * AP + k4 * 4];
                d[0] = v.x; d[1] = v.y; d[2] = v.z; d[3] = v.w;
            }
        }
        // ---- stage B (weights already tf32) ----
        {
            constexpr int N4 = 32 * OUT / 4;
#pragma unroll
            for (int i = tid; i < N4; i += 256) {
                int kk = i / (OUT / 4);
                int n4 = i % (OUT / 4);
                float4 wv = *reinterpret_cast<const float4*>(&Wt[(size_t)(k0 + kk) * OUT + n4 * 4]);
                *reinterpret_cast<float4*>(&Bs[kk * BP + n4 * 4]) = wv;
            }
        }
        __syncthreads();

        // ---- mma ----
#pragma unroll
        for (int ks = 0; ks < 4; ks++) {
            const int kb = ks * 8;
            uint32_t a[2][4];
#pragma unroll
            for (int ms = 0; ms < 2; ms++) {
                int r = warpM * 32 + ms * 16 + g;
                a[ms][0] = f2tf32(As[r * AP + kb + t4]);
                a[ms][1] = f2tf32(As[(r + 8) * AP + kb + t4]);
                a[ms][2] = f2tf32(As[r * AP + kb + t4 + 4]);
                a[ms][3] = f2tf32(As[(r + 8) * AP + kb + t4 + 4]);
            }
#pragma unroll
            for (int ns = 0; ns < NS; ns++) {
                int c = warpN * (OUT / 2) + ns * 8 + g;
                uint32_t b0 = __float_as_uint(Bs[(kb + t4) * BP + c]);
                uint32_t b1 = __float_as_uint(Bs[(kb + t4 + 4) * BP + c]);
                MMA_TF32(acc[0][ns], a[0], b0, b1);
                MMA_TF32(acc[1][ns], a[1], b0, b1);
            }
        }
        __syncthreads();
    }

    // ---- epilogue: bias + act + float2 stores ----
#pragma unroll
    for (int ms = 0; ms < 2; ms++) {
#pragma unroll
        for (int ns = 0; ns < NS; ns++) {
            int col  = warpN * (OUT / 2) + ns * 8 + t4 * 2;
            int row0 = node0 + warpM * 32 + ms * 16 + g;
            float bx = bs[col], by = bs[col + 1];
#pragma unroll
            for (int h = 0; h < 2; h++) {
                int row = row0 + h * 8;
                if (row < N_NODES) {
                    float2 r;
                    r.x = acc[ms][ns][h * 2 + 0] + bx;
                    r.y = acc[ms][ns][h * 2 + 1] + by;
                    if (RELU) { r.x = fmaxf(r.x, 0.f); r.y = fmaxf(r.y, 0.f); }
                    *reinterpret_cast<float2*>(&out[(size_t)row * OUT + col]) = r;
                }
            }
        }
    }
}

// ---------------- host launcher ----------------
extern "C" void kernel_launch(void* const* d_in, const int* in_sizes, int n_in,
                              void* d_out, int out_size) {
    // size-class input identification (ordering-agnostic)
    const float* x = nullptr;
    const int*   edge[2] = {nullptr, nullptr};
    const float* w16[4]  = {nullptr, nullptr, nullptr, nullptr};
    const float* w8[2]   = {nullptr, nullptr};
    const float* b128[2] = {nullptr, nullptr};
    const float* b2 = nullptr;
    int ne = 0, n16 = 0, n8 = 0, nb = 0;
    int x_slot = -1;

    for (int i = 0; i < n_in && i < 12; i++) {
        int sz = in_sizes[i];
        if (sz == N_NODES * DIM)      { x = (const float*)d_in[i]; x_slot = i; }
        else if (sz == N_EDGES)       { if (ne < 2)  edge[ne++] = (const int*)d_in[i]; }
        else if (sz == DIM * DIM)     { if (n16 < 4) w16[n16++] = (const float*)d_in[i]; }
        else if (sz == DIM * 64)      { if (n8 < 2)  w8[n8++]   = (const float*)d_in[i]; }
        else if (sz == DIM)           { if (nb < 2)  b128[nb++] = (const float*)d_in[i]; }
        else if (sz == 64)            { b2 = (const float*)d_in[i]; }
    }

    const float *Ws0, *Wn0, *b0, *Ws1, *Wn1, *b1, *Ws2, *Wn2;
    const int *src, *dst;
    if (x_slot == 0) {
        src = edge[0]; dst = edge[1];
        Ws0 = w16[0]; Wn0 = w16[1]; Ws1 = w16[2]; Wn1 = w16[3];
        Ws2 = w8[0];  Wn2 = w8[1];
    } else {
        dst = edge[0]; src = edge[1];
        Wn0 = w16[0]; Wn1 = w16[1]; Ws0 = w16[2]; Ws1 = w16[3];
        Wn2 = w8[0];  Ws2 = w8[1];
    }
    b0 = b128[0]; b1 = b128[1];
    float* out = (float*)d_out;

    const int SMEM128 = (128 * 36 + 32 * 136 + 128) * 4;   // 36352 B
    const int SMEM64  = (128 * 36 + 32 * 72  + 64) * 4;    // 27904 B

    const int NB = (N_NODES + 255) / 256;            // 196
    const int AGG_BLOCKS  = (N_NODES * 32 + 255) / 256;
    const int GEMM_BLOCKS = (N_NODES + 127) / 128;   // 391

    // ---- prep (zero counts + bsum + tf32 weights) ----
    prep_kernel<<<320, 256>>>(Ws0, Wn0, Ws1, Wn1, Ws2, Wn2);

    // ---- CSR build (by dst): hist(+bsum) -> partials -> block_scan -> scatter ----
    hist_kernel<<<(N_EDGES + 255) / 256, 256>>>(dst);
    scan_partials_kernel<<<1, 256>>>();
    block_scan_kernel<<<NB, 256>>>();
    scatter_kernel<<<(N_EDGES + 255) / 256, 256>>>(src, dst);

    // ---- layer 0: x -> g_h1 ----
    aggregate_kernel<0><<<AGG_BLOCKS, 256>>>(x);
    gemm_tc_kernel<128, true, 0, 1, 0><<<GEMM_BLOCKS, 256, SMEM128>>>(x, b0, nullptr);

    // ---- layer 1: g_h1 -> g_h2 ----
    aggregate_kernel<1><<<AGG_BLOCKS, 256>>>(nullptr);
    gemm_tc_kernel<128, true, 1, 2, 1><<<GEMM_BLOCKS, 256, SMEM128>>>(nullptr, b1, nullptr);

    // ---- layer 2: g_h2 -> out ----
    aggregate_kernel<2><<<AGG_BLOCKS, 256>>>(nullptr);
    gemm_tc_kernel<64, false, 2, 0, 2><<<GEMM_BLOCKS, 256, SMEM64>>>(nullptr, b2, out);
}

// round 16
// speedup vs baseline: 1.9434x; 1.9434x over previous
#include <cuda_runtime.h>
#include <cuda_bf16.h>
#include <cstdint>

#define N_NODES 50000
#define N_EDGES 800000
#define DIM 128

// ---------------- device scratch (no allocations allowed) ----------------
__device__ int   g_count[N_NODES];
__device__ int   g_rowptr[N_NODES + 1];
__device__ int   g_esrc[N_EDGES];
__device__ int   g_bsum[256];
__device__ int   g_boff[256];
__device__ float g_agg[N_NODES * DIM];
__device__ float g_h1[N_NODES * DIM];
__device__ float g_h2[N_NODES * DIM];
__device__ float g_wt0[256 * 128];     // tf32-rounded [Wself0;Wneigh0]
__device__ float g_wt1[256 * 128];
__device__ float g_wt2[256 * 64];

__device__ __forceinline__ uint32_t f2tf32(float f) {
    uint32_t u;
    asm("cvt.rna.tf32.f32 %0, %1;" : "=r"(u) : "f"(f));
    return u;
}

#define MMA_TF32(c, a, b0, b1)                                               \
    asm volatile("mma.sync.aligned.m16n8k8.row.col.f32.tf32.tf32.f32 "       \
        "{%0,%1,%2,%3}, {%4,%5,%6,%7}, {%8,%9}, {%0,%1,%2,%3};"              \
        : "+f"((c)[0]), "+f"((c)[1]), "+f"((c)[2]), "+f"((c)[3])             \
        : "r"((a)[0]), "r"((a)[1]), "r"((a)[2]), "r"((a)[3]),                \
          "r"(b0), "r"(b1))

// ---------------- prep: zero counts + tf32 weights (fused, proven safe) ----------------
__global__ void prep_kernel(const float* __restrict__ Ws0, const float* __restrict__ Wn0,
                            const float* __restrict__ Ws1, const float* __restrict__ Wn1,
                            const float* __restrict__ Ws2, const float* __restrict__ Wn2) {
    int i = blockIdx.x * blockDim.x + threadIdx.x;
    if (i < N_NODES) g_count[i] = 0;
    if (i < 256 * 128) {
        int k = i / 128, o = i % 128;
        float v0 = (k < 128) ? Ws0[k * 128 + o] : Wn0[(k - 128) * 128 + o];
        float v1 = (k < 128) ? Ws1[k * 128 + o] : Wn1[(k - 128) * 128 + o];
        g_wt0[i] = __uint_as_float(f2tf32(v0));
        g_wt1[i] = __uint_as_float(f2tf32(v1));
    }
    if (i < 256 * 64) {
        int k = i / 64, o = i % 64;
        float v2 = (k < 128) ? Ws2[k * 64 + o] : Wn2[(k - 128) * 64 + o];
        g_wt2[i] = __uint_as_float(f2tf32(v2));
    }
}

// ---------------- CSR build (R10 structure: single atomic per edge) ----------------
__global__ void hist_kernel(const int* __restrict__ dst) {
    int e = blockIdx.x * blockDim.x + threadIdx.x;
    if (e < N_EDGES) {
        unsigned d = (unsigned)dst[e];
        if (d < N_NODES) atomicAdd(&g_count[d], 1);
    }
}

__device__ __forceinline__ int block_incl_scan256(int v, int* wsum) {
    int lane = threadIdx.x & 31, w = threadIdx.x >> 5;
    int s = v;
#pragma unroll
    for (int off = 1; off < 32; off <<= 1) {
        int x = __shfl_up_sync(0xFFFFFFFFu, s, off);
        if (lane >= off) s += x;
    }
    if (lane == 31) wsum[w] = s;
    __syncthreads();
    if (w == 0) {
        int ws = (lane < 8) ? wsum[lane] : 0;
#pragma unroll
        for (int off = 1; off < 8; off <<= 1) {
            int x = __shfl_up_sync(0xFFFFFFFFu, ws, off);
            if (lane >= off) ws += x;
        }
        if (lane < 8) wsum[lane] = ws;
    }
    __syncthreads();
    return s + ((w > 0) ? wsum[w - 1] : 0);
}

__global__ void reduce_counts_kernel() {       // 196 x 256
    __shared__ int wsum[8];
    int i = blockIdx.x * 256 + threadIdx.x;
    int v = (i < N_NODES) ? g_count[i] : 0;
    int incl = block_incl_scan256(v, wsum);
    if (threadIdx.x == 255) g_bsum[blockIdx.x] = incl;
}

__global__ void scan_partials_kernel() {       // 1 x 256
    __shared__ int wsum[8];
    int t = threadIdx.x;
    int v = (t < 196) ? g_bsum[t] : 0;
    int incl = block_incl_scan256(v, wsum);
    if (t < 196) g_boff[t] = incl - v;
}

__global__ void block_scan_kernel() {          // 196 x 256; writes rowptr + cursor
    __shared__ int wsum[8];
    int i = blockIdx.x * 256 + threadIdx.x;
    int v = (i < N_NODES) ? g_count[i] : 0;
    int incl = block_incl_scan256(v, wsum);
    if (i < N_NODES) {
        int excl = g_boff[blockIdx.x] + incl - v;
        g_rowptr[i + 1] = excl + v;
        g_count[i] = excl;
    }
    if (i == 0) g_rowptr[0] = 0;
}

__global__ void scatter_kernel(const int* __restrict__ src, const int* __restrict__ dst) {
    int e = blockIdx.x * blockDim.x + threadIdx.x;
    if (e < N_EDGES) {
        unsigned d = (unsigned)dst[e];
        unsigned s = (unsigned)src[e];
        if (d < N_NODES && s < N_NODES) {
            int pos = atomicAdd(&g_count[d], 1);
            if ((unsigned)pos < N_EDGES) g_esrc[pos] = (int)s;
        }
    }
}

// ---------------- mean aggregation: one warp per node, SIMPLE loop (MLP_p1=1) ----
// Proven optimal: x4-unroll inflates cross-CTA L1tex-queue spread (R15 regression);
// fp16 operands neutral-to-worse (R13). This shape measures at the L2 gather roofline.
template <int HSEL>
__global__ void aggregate_kernel(const float* __restrict__ hext) {
    const float* __restrict__ h =
        (HSEL == 0) ? hext : ((HSEL == 1) ? (const float*)g_h1 : (const float*)g_h2);
    int warp = (blockIdx.x * blockDim.x + threadIdx.x) >> 5;
    int lane = threadIdx.x & 31;
    if (warp >= N_NODES) return;
    int beg = g_rowptr[warp];
    int end = g_rowptr[warp + 1];
    float ax = 0.f, ay = 0.f, az = 0.f, aw = 0.f;
    for (int i = beg; i < end; i++) {
        int s = g_esrc[i];
        float4 v = *reinterpret_cast<const float4*>(&h[(size_t)s * DIM + lane * 4]);
        ax += v.x; ay += v.y; az += v.z; aw += v.w;
    }
    float inv = (end > beg) ? (1.0f / (float)(end - beg)) : 0.0f;
    float4 r; r.x = ax * inv; r.y = ay * inv; r.z = az * inv; r.w = aw * inv;
    *reinterpret_cast<float4*>(&g_agg[(size_t)warp * DIM + lane * 4]) = r;
}

// ---------------- fused GEMM (tf32 mma): full K=256, A = [hin | g_agg] ----------------
// Block: 256 threads (8 warps), tile 128 nodes x OUT, warp grid 4Mx2N, m16n8k8.
template <int OUT, bool RELU, int HSEL, int DSEL, int WSEL>
__global__ __launch_bounds__(256)
void gemm_tc_kernel(const float* __restrict__ hinext,
                    const float* __restrict__ bias, float* __restrict__ outext) {
    const float* __restrict__ hin =
        (HSEL == 0) ? hinext : ((HSEL == 1) ? (const float*)g_h1 : (const float*)g_h2);
    float* __restrict__ out =
        (DSEL == 0) ? outext : ((DSEL == 1) ? (float*)g_h1 : (float*)g_h2);
    const float* __restrict__ Wt =
        (WSEL == 0) ? g_wt0 : (WSEL == 1) ? g_wt1 : g_wt2;

    constexpr int AP = 36;
    constexpr int BP = OUT + 8;
    constexpr int NS = OUT / 16;

    extern __shared__ float smem[];
    float* As = smem;                  // [128][AP]
    float* Bs = smem + 128 * AP;       // [32][BP]
    float* bs = Bs + 32 * BP;          // [OUT]

    const int tid   = threadIdx.x;
    const int lane  = tid & 31;
    const int wid   = tid >> 5;
    const int g     = lane >> 2;
    const int t4    = lane & 3;
    const int warpM = wid & 3;
    const int warpN = wid >> 2;
    const int node0 = blockIdx.x * 128;

    if (tid < OUT) bs[tid] = bias[tid];

    float acc[2][NS][4];
#pragma unroll
    for (int ms = 0; ms < 2; ms++)
#pragma unroll
        for (int ns = 0; ns < NS; ns++)
#pragma unroll
            for (int c = 0; c < 4; c++) acc[ms][ns][c] = 0.f;

    for (int kt = 0; kt < 8; kt++) {
        const int k0 = kt * 32;
        // ---- stage A: [hin | g_agg] ----
        {
            const float* srcb = (k0 < 128) ? hin : (const float*)g_agg;
            const int koff = (k0 < 128) ? k0 : (k0 - 128);
            const float4 z4 = make_float4(0.f, 0.f, 0.f, 0.f);
#pragma unroll
            for (int i = tid; i < 1024; i += 256) {
                int j  = i >> 3;
                int k4 = i & 7;
                int n  = node0 + j;
                float4 v = (n < N_NODES)
                    ? *reinterpret_cast<const float4*>(&srcb[(size_t)n * DIM + koff + k4 * 4])
                    : z4;
                float* d = &As[j * AP + k4 * 4];
                d[0] = v.x; d[1] = v.y; d[2] = v.z; d[3] = v.w;
            }
        }
        // ---- stage B (weights already tf32) ----
        {
            constexpr int N4 = 32 * OUT / 4;
#pragma unroll
            for (int i = tid; i < N4; i += 256) {
                int kk = i / (OUT / 4);
                int n4 = i % (OUT / 4);
                float4 wv = *reinterpret_cast<const float4*>(&Wt[(size_t)(k0 + kk) * OUT + n4 * 4]);
                *reinterpret_cast<float4*>(&Bs[kk * BP + n4 * 4]) = wv;
            }
        }
        __syncthreads();

        // ---- mma ----
#pragma unroll
        for (int ks = 0; ks < 4; ks++) {
            const int kb = ks * 8;
            uint32_t a[2][4];
#pragma unroll
            for (int ms = 0; ms < 2; ms++) {
                int r = warpM * 32 + ms * 16 + g;
                a[ms][0] = f2tf32(As[r * AP + kb + t4]);
                a[ms][1] = f2tf32(As[(r + 8) * AP + kb + t4]);
                a[ms][2] = f2tf32(As[r * AP + kb + t4 + 4]);
                a[ms][3] = f2tf32(As[(r + 8) * AP + kb + t4 + 4]);
            }
#pragma unroll
            for (int ns = 0; ns < NS; ns++) {
                int c = warpN * (OUT / 2) + ns * 8 + g;
                uint32_t b0 = __float_as_uint(Bs[(kb + t4) * BP + c]);
                uint32_t b1 = __float_as_uint(Bs[(kb + t4 + 4) * BP + c]);
                MMA_TF32(acc[0][ns], a[0], b0, b1);
                MMA_TF32(acc[1][ns], a[1], b0, b1);
            }
        }
        __syncthreads();
    }

    // ---- epilogue: bias + act + float2 stores ----
#pragma unroll
    for (int ms = 0; ms < 2; ms++) {
#pragma unroll
        for (int ns = 0; ns < NS; ns++) {
            int col  = warpN * (OUT / 2) + ns * 8 + t4 * 2;
            int row0 = node0 + warpM * 32 + ms * 16 + g;
            float bx = bs[col], by = bs[col + 1];
#pragma unroll
            for (int h = 0; h < 2; h++) {
                int row = row0 + h * 8;
                if (row < N_NODES) {
                    float2 r;
                    r.x = acc[ms][ns][h * 2 + 0] + bx;
                    r.y = acc[ms][ns][h * 2 + 1] + by;
                    if (RELU) { r.x = fmaxf(r.x, 0.f); r.y = fmaxf(r.y, 0.f); }
                    *reinterpret_cast<float2*>(&out[(size_t)row * OUT + col]) = r;
                }
            }
        }
    }
}

// ---------------- host launcher ----------------
extern "C" void kernel_launch(void* const* d_in, const int* in_sizes, int n_in,
                              void* d_out, int out_size) {
    // size-class input identification (ordering-agnostic)
    const float* x = nullptr;
    const int*   edge[2] = {nullptr, nullptr};
    const float* w16[4]  = {nullptr, nullptr, nullptr, nullptr};
    const float* w8[2]   = {nullptr, nullptr};
    const float* b128[2] = {nullptr, nullptr};
    const float* b2 = nullptr;
    int ne = 0, n16 = 0, n8 = 0, nb = 0;
    int x_slot = -1;

    for (int i = 0; i < n_in && i < 12; i++) {
        int sz = in_sizes[i];
        if (sz == N_NODES * DIM)      { x = (const float*)d_in[i]; x_slot = i; }
        else if (sz == N_EDGES)       { if (ne < 2)  edge[ne++] = (const int*)d_in[i]; }
        else if (sz == DIM * DIM)     { if (n16 < 4) w16[n16++] = (const float*)d_in[i]; }
        else if (sz == DIM * 64)      { if (n8 < 2)  w8[n8++]   = (const float*)d_in[i]; }
        else if (sz == DIM)           { if (nb < 2)  b128[nb++] = (const float*)d_in[i]; }
        else if (sz == 64)            { b2 = (const float*)d_in[i]; }
    }

    const float *Ws0, *Wn0, *b0, *Ws1, *Wn1, *b1, *Ws2, *Wn2;
    const int *src, *dst;
    if (x_slot == 0) {
        src = edge[0]; dst = edge[1];
        Ws0 = w16[0]; Wn0 = w16[1]; Ws1 = w16[2]; Wn1 = w16[3];
        Ws2 = w8[0];  Wn2 = w8[1];
    } else {
        dst = edge[0]; src = edge[1];
        Wn0 = w16[0]; Wn1 = w16[1]; Ws0 = w16[2]; Ws1 = w16[3];
        Wn2 = w8[0];  Ws2 = w8[1];
    }
    b0 = b128[0]; b1 = b128[1];
    float* out = (float*)d_out;

    const int SMEM128 = (128 * 36 + 32 * 136 + 128) * 4;   // 36352 B
    const int SMEM64  = (128 * 36 + 32 * 72  + 64) * 4;    // 27904 B

    const int NB = (N_NODES + 255) / 256;            // 196
    const int AGG_BLOCKS  = (N_NODES * 32 + 255) / 256;
    const int GEMM_BLOCKS = (N_NODES + 127) / 128;   // 391

    // ---- prep (zero counts + tf32 weights) ----
    prep_kernel<<<320, 256>>>(Ws0, Wn0, Ws1, Wn1, Ws2, Wn2);

    // ---- CSR build (by dst) ----
    hist_kernel<<<(N_EDGES + 255) / 256, 256>>>(dst);
    reduce_counts_kernel<<<NB, 256>>>();
    scan_partials_kernel<<<1, 256>>>();
    block_scan_kernel<<<NB, 256>>>();
    scatter_kernel<<<(N_EDGES + 255) / 256, 256>>>(src, dst);

    // ---- layer 0: x -> g_h1 ----
    aggregate_kernel<0><<<AGG_BLOCKS, 256>>>(x);
    gemm_tc_kernel<128, true, 0, 1, 0><<<GEMM_BLOCKS, 256, SMEM128>>>(x, b0, nullptr);

    // ---- layer 1: g_h1 -> g_h2 ----
    aggregate_kernel<1><<<AGG_BLOCKS, 256>>>(nullptr);
    gemm_tc_kernel<128, true, 1, 2, 1><<<GEMM_BLOCKS, 256, SMEM128>>>(nullptr, b1, nullptr);

    // ---- layer 2: g_h2 -> out ----
    aggregate_kernel<2><<<AGG_BLOCKS, 256>>>(nullptr);
    gemm_tc_kernel<64, false, 2, 0, 2><<<GEMM_BLOCKS, 256, SMEM64>>>(nullptr, b2, out);
}

// round 17
// speedup vs baseline: 2.1684x; 1.1158x over previous
#include <cuda_runtime.h>
#include <cuda_bf16.h>
#include <cstdint>

#define N_NODES 50000
#define N_EDGES 800000
#define DIM 128

// ---------------- device scratch (no allocations allowed) ----------------
__device__ int   g_count[N_NODES];
__device__ int   g_rowptr[N_NODES + 1];
__device__ int   g_esrc[N_EDGES];
__device__ int   g_bsum[256];
__device__ int   g_boff[256];
__device__ float g_x  [N_NODES * DIM];   // tf32-rounded copy of x
__device__ float g_agg[N_NODES * DIM];   // tf32-rounded agg
__device__ float g_h1 [N_NODES * DIM];   // tf32-rounded hidden
__device__ float g_h2 [N_NODES * DIM];
__device__ float g_wt0[256 * 128];       // tf32-rounded [Wself0;Wneigh0]
__device__ float g_wt1[256 * 128];
__device__ float g_wt2[256 * 64];

__device__ __forceinline__ uint32_t f2tf32(float f) {
    uint32_t u;
    asm("cvt.rna.tf32.f32 %0, %1;" : "=r"(u) : "f"(f));
    return u;
}
__device__ __forceinline__ float rnd_tf32(float f) { return __uint_as_float(f2tf32(f)); }

#define MMA_TF32(c, a, b0, b1)                                               \
    asm volatile("mma.sync.aligned.m16n8k8.row.col.f32.tf32.tf32.f32 "       \
        "{%0,%1,%2,%3}, {%4,%5,%6,%7}, {%8,%9}, {%0,%1,%2,%3};"              \
        : "+f"((c)[0]), "+f"((c)[1]), "+f"((c)[2]), "+f"((c)[3])             \
        : "r"((a)[0]), "r"((a)[1]), "r"((a)[2]), "r"((a)[3]),                \
          "r"(b0), "r"(b1))

#define CP_ASYNC16(dst_u32, src_ptr, sz) \
    asm volatile("cp.async.cg.shared.global [%0], [%1], 16, %2;" \
        :: "r"(dst_u32), "l"(src_ptr), "r"(sz))
#define CP_COMMIT()  asm volatile("cp.async.commit_group;")
#define CP_WAIT(N)   asm volatile("cp.async.wait_group %0;" :: "n"(N))

// ---------------- prep: zero counts + tf32 weights + tf32 copy of x ----------------
__global__ void prep_kernel(const float* __restrict__ x,
                            const float* __restrict__ Ws0, const float* __restrict__ Wn0,
                            const float* __restrict__ Ws1, const float* __restrict__ Wn1,
                            const float* __restrict__ Ws2, const float* __restrict__ Wn2) {
    int i = blockIdx.x * blockDim.x + threadIdx.x;
    if (i < N_NODES) g_count[i] = 0;
    if (i < 256 * 128) {
        int k = i / 128, o = i % 128;
        float v0 = (k < 128) ? Ws0[k * 128 + o] : Wn0[(k - 128) * 128 + o];
        float v1 = (k < 128) ? Ws1[k * 128 + o] : Wn1[(k - 128) * 128 + o];
        g_wt0[i] = rnd_tf32(v0);
        g_wt1[i] = rnd_tf32(v1);
    }
    if (i < 256 * 64) {
        int k = i / 64, o = i % 64;
        float v2 = (k < 128) ? Ws2[k * 64 + o] : Wn2[(k - 128) * 64 + o];
        g_wt2[i] = rnd_tf32(v2);
    }
    // x -> tf32-rounded copy (vectorized strided loop)
    const int N4 = N_NODES * DIM / 4;
    const int stride = gridDim.x * blockDim.x;
    for (int j = i; j < N4; j += stride) {
        float4 v = reinterpret_cast<const float4*>(x)[j];
        v.x = rnd_tf32(v.x); v.y = rnd_tf32(v.y);
        v.z = rnd_tf32(v.z); v.w = rnd_tf32(v.w);
        reinterpret_cast<float4*>(g_x)[j] = v;
    }
}

// ---------------- CSR build ----------------
__global__ void hist_kernel(const int* __restrict__ dst) {
    int e = blockIdx.x * blockDim.x + threadIdx.x;
    if (e < N_EDGES) {
        unsigned d = (unsigned)dst[e];
        if (d < N_NODES) atomicAdd(&g_count[d], 1);
    }
}

__device__ __forceinline__ int block_incl_scan256(int v, int* wsum) {
    int lane = threadIdx.x & 31, w = threadIdx.x >> 5;
    int s = v;
#pragma unroll
    for (int off = 1; off < 32; off <<= 1) {
        int x = __shfl_up_sync(0xFFFFFFFFu, s, off);
        if (lane >= off) s += x;
    }
    if (lane == 31) wsum[w] = s;
    __syncthreads();
    if (w == 0) {
        int ws = (lane < 8) ? wsum[lane] : 0;
#pragma unroll
        for (int off = 1; off < 8; off <<= 1) {
            int x = __shfl_up_sync(0xFFFFFFFFu, ws, off);
            if (lane >= off) ws += x;
        }
        if (lane < 8) wsum[lane] = ws;
    }
    __syncthreads();
    return s + ((w > 0) ? wsum[w - 1] : 0);
}

__global__ void reduce_counts_kernel() {       // 196 x 256
    __shared__ int wsum[8];
    int i = blockIdx.x * 256 + threadIdx.x;
    int v = (i < N_NODES) ? g_count[i] : 0;
    int incl = block_incl_scan256(v, wsum);
    if (threadIdx.x == 255) g_bsum[blockIdx.x] = incl;
}

__global__ void scan_partials_kernel() {       // 1 x 256
    __shared__ int wsum[8];
    int t = threadIdx.x;
    int v = (t < 196) ? g_bsum[t] : 0;
    int incl = block_incl_scan256(v, wsum);
    if (t < 196) g_boff[t] = incl - v;
}

__global__ void block_scan_kernel() {          // 196 x 256; writes rowptr + cursor
    __shared__ int wsum[8];
    int i = blockIdx.x * 256 + threadIdx.x;
    int v = (i < N_NODES) ? g_count[i] : 0;
    int incl = block_incl_scan256(v, wsum);
    if (i < N_NODES) {
        int excl = g_boff[blockIdx.x] + incl - v;
        g_rowptr[i + 1] = excl + v;
        g_count[i] = excl;
    }
    if (i == 0) g_rowptr[0] = 0;
}

__global__ void scatter_kernel(const int* __restrict__ src, const int* __restrict__ dst) {
    int e = blockIdx.x * blockDim.x + threadIdx.x;
    if (e < N_EDGES) {
        unsigned d = (unsigned)dst[e];
        unsigned s = (unsigned)src[e];
        if (d < N_NODES && s < N_NODES) {
            int pos = atomicAdd(&g_count[d], 1);
            if ((unsigned)pos < N_EDGES) g_esrc[pos] = (int)s;
        }
    }
}

// ---------------- mean aggregation: one warp per node, simple loop (proven optimal) ----
// Output rounded to tf32 so the GEMM can consume it without conversion.
template <int HSEL>
__global__ void aggregate_kernel(const float* __restrict__ hext) {
    const float* __restrict__ h =
        (HSEL == 0) ? hext : ((HSEL == 1) ? (const float*)g_h1 : (const float*)g_h2);
    int warp = (blockIdx.x * blockDim.x + threadIdx.x) >> 5;
    int lane = threadIdx.x & 31;
    if (warp >= N_NODES) return;
    int beg = g_rowptr[warp];
    int end = g_rowptr[warp + 1];
    float ax = 0.f, ay = 0.f, az = 0.f, aw = 0.f;
    for (int i = beg; i < end; i++) {
        int s = g_esrc[i];
        float4 v = *reinterpret_cast<const float4*>(&h[(size_t)s * DIM + lane * 4]);
        ax += v.x; ay += v.y; az += v.z; aw += v.w;
    }
    float inv = (end > beg) ? (1.0f / (float)(end - beg)) : 0.0f;
    float4 r;
    r.x = rnd_tf32(ax * inv); r.y = rnd_tf32(ay * inv);
    r.z = rnd_tf32(az * inv); r.w = rnd_tf32(aw * inv);
    *reinterpret_cast<float4*>(&g_agg[(size_t)warp * DIM + lane * 4]) = r;
}

// ---------------- fused GEMM (tf32 mma): cp.async double-buffered pipeline ----------
// A = [hsel | g_agg], both already tf32-rounded -> no converts in the hot loop.
// Block: 256 threads (8 warps), tile 128 nodes x OUT, warp grid 4Mx2N, m16n8k8.
// HSEL: 0=g_x, 1=g_h1, 2=g_h2.  DSEL: 0=ext(fp32), 1=g_h1(tf32), 2=g_h2(tf32).
template <int OUT, bool RELU, int HSEL, int DSEL, int WSEL>
__global__ __launch_bounds__(256)
void gemm_tc_kernel(const float* __restrict__ bias, float* __restrict__ outext) {
    const float* __restrict__ hin =
        (HSEL == 0) ? (const float*)g_x :
        (HSEL == 1) ? (const float*)g_h1 : (const float*)g_h2;
    float* __restrict__ out =
        (DSEL == 0) ? outext : ((DSEL == 1) ? (float*)g_h1 : (float*)g_h2);
    const float* __restrict__ Wt =
        (WSEL == 0) ? g_wt0 : (WSEL == 1) ? g_wt1 : g_wt2;

    constexpr int AP  = 36;
    constexpr int BP  = OUT + 8;
    constexpr int NS  = OUT / 16;
    constexpr int ASZ = 128 * AP;      // floats per A buffer
    constexpr int BSZ = 32 * BP;       // floats per B buffer

    extern __shared__ float smem[];
    float* As = smem;                  // [2][128][AP]
    float* Bs = smem + 2 * ASZ;        // [2][32][BP]
    float* bs = Bs + 2 * BSZ;          // [OUT]

    const uint32_t As_u = (uint32_t)__cvta_generic_to_shared(As);
    const uint32_t Bs_u = (uint32_t)__cvta_generic_to_shared(Bs);

    const int tid   = threadIdx.x;
    const int lane  = tid & 31;
    const int wid   = tid >> 5;
    const int g     = lane >> 2;
    const int t4    = lane & 3;
    const int warpM = wid & 3;
    const int warpN = wid >> 2;
    const int node0 = blockIdx.x * 128;

    if (tid < OUT) bs[tid] = bias[tid];

    // stage issuers (cp.async, zfill-predicated)
    auto stage = [&](int kt, int buf) {
        const int k0 = kt * 32;
        const float* srcb = (k0 < 128) ? hin : (const float*)g_agg;
        const int koff = (k0 < 128) ? k0 : (k0 - 128);
        // A: 128 rows x 8 float4
#pragma unroll
        for (int i = tid; i < 1024; i += 256) {
            int j  = i >> 3;
            int k4 = i & 7;
            int n  = node0 + j;
            int nc = (n < N_NODES) ? n : (N_NODES - 1);
            int sz = (n < N_NODES) ? 16 : 0;
            uint32_t d = As_u + (uint32_t)(buf * ASZ + j * AP + k4 * 4) * 4u;
            CP_ASYNC16(d, &srcb[(size_t)nc * DIM + koff + k4 * 4], sz);
        }
        // B: 32 rows x OUT/4 float4
        constexpr int N4 = 32 * OUT / 4;
#pragma unroll
        for (int i = tid; i < N4; i += 256) {
            int kk = i / (OUT / 4);
            int n4 = i % (OUT / 4);
            uint32_t d = Bs_u + (uint32_t)(buf * BSZ + kk * BP + n4 * 4) * 4u;
            CP_ASYNC16(d, &Wt[(size_t)(k0 + kk) * OUT + n4 * 4], 16);
        }
        CP_COMMIT();
    };

    float acc[2][NS][4];
#pragma unroll
    for (int ms = 0; ms < 2; ms++)
#pragma unroll
        for (int ns = 0; ns < NS; ns++)
#pragma unroll
            for (int c = 0; c < 4; c++) acc[ms][ns][c] = 0.f;

    stage(0, 0);

    for (int kt = 0; kt < 8; kt++) {
        const int buf = kt & 1;
        if (kt < 7) { stage(kt + 1, buf ^ 1); CP_WAIT(1); }
        else        { CP_WAIT(0); }
        __syncthreads();

        const float* Ab = As + buf * ASZ;
        const float* Bb = Bs + buf * BSZ;
#pragma unroll
        for (int ks = 0; ks < 4; ks++) {
            const int kb = ks * 8;
            uint32_t a[2][4];
#pragma unroll
            for (int ms = 0; ms < 2; ms++) {
                int r = warpM * 32 + ms * 16 + g;
                a[ms][0] = __float_as_uint(Ab[r * AP + kb + t4]);
                a[ms][1] = __float_as_uint(Ab[(r + 8) * AP + kb + t4]);
                a[ms][2] = __float_as_uint(Ab[r * AP + kb + t4 + 4]);
                a[ms][3] = __float_as_uint(Ab[(r + 8) * AP + kb + t4 + 4]);
            }
#pragma unroll
            for (int ns = 0; ns < NS; ns++) {
                int c = warpN * (OUT / 2) + ns * 8 + g;
                uint32_t b0 = __float_as_uint(Bb[(kb + t4) * BP + c]);
                uint32_t b1 = __float_as_uint(Bb[(kb + t4 + 4) * BP + c]);
                MMA_TF32(acc[0][ns], a[0], b0, b1);
                MMA_TF32(acc[1][ns], a[1], b0, b1);
            }
        }
        __syncthreads();   // protect buf from next prefetch overwrite
    }

    // ---- epilogue: bias + act (+ tf32 rounding for intermediates) ----
#pragma unroll
    for (int ms = 0; ms < 2; ms++) {
#pragma unroll
        for (int ns = 0; ns < NS; ns++) {
            int col  = warpN * (OUT / 2) + ns * 8 + t4 * 2;
            int row0 = node0 + warpM * 32 + ms * 16 + g;
            float bx = bs[col], by = bs[col + 1];
#pragma unroll
            for (int h = 0; h < 2; h++) {
                int row = row0 + h * 8;
                if (row < N_NODES) {
                    float2 r;
                    r.x = acc[ms][ns][h * 2 + 0] + bx;
                    r.y = acc[ms][ns][h * 2 + 1] + by;
                    if (RELU) { r.x = fmaxf(r.x, 0.f); r.y = fmaxf(r.y, 0.f); }
                    if (DSEL != 0) { r.x = rnd_tf32(r.x); r.y = rnd_tf32(r.y); }
                    *reinterpret_cast<float2*>(&out[(size_t)row * OUT + col]) = r;
                }
            }
        }
    }
}

// ---------------- host launcher ----------------
extern "C" void kernel_launch(void* const* d_in, const int* in_sizes, int n_in,
                              void* d_out, int out_size) {
    // size-class input identification (ordering-agnostic)
    const float* x = nullptr;
    const int*   edge[2] = {nullptr, nullptr};
    const float* w16[4]  = {nullptr, nullptr, nullptr, nullptr};
    const float* w8[2]   = {nullptr, nullptr};
    const float* b128[2] = {nullptr, nullptr};
    const float* b2 = nullptr;
    int ne = 0, n16 = 0, n8 = 0, nb = 0;
    int x_slot = -1;

    for (int i = 0; i < n_in && i < 12; i++) {
        int sz = in_sizes[i];
        if (sz == N_NODES * DIM)      { x = (const float*)d_in[i]; x_slot = i; }
        else if (sz == N_EDGES)       { if (ne < 2)  edge[ne++] = (const int*)d_in[i]; }
        else if (sz == DIM * DIM)     { if (n16 < 4) w16[n16++] = (const float*)d_in[i]; }
        else if (sz == DIM * 64)      { if (n8 < 2)  w8[n8++]   = (const float*)d_in[i]; }
        else if (sz == DIM)           { if (nb < 2)  b128[nb++] = (const float*)d_in[i]; }
        else if (sz == 64)            { b2 = (const float*)d_in[i]; }
    }

    const float *Ws0, *Wn0, *b0, *Ws1, *Wn1, *b1, *Ws2, *Wn2;
    const int *src, *dst;
    if (x_slot == 0) {
        src = edge[0]; dst = edge[1];
        Ws0 = w16[0]; Wn0 = w16[1]; Ws1 = w16[2]; Wn1 = w16[3];
        Ws2 = w8[0];  Wn2 = w8[1];
    } else {
        dst = edge[0]; src = edge[1];
        Wn0 = w16[0]; Wn1 = w16[1]; Ws0 = w16[2]; Ws1 = w16[3];
        Wn2 = w8[0];  Ws2 = w8[1];
    }
    b0 = b128[0]; b1 = b128[1];
    float* out = (float*)d_out;

    // smem: 2*As + 2*Bs + bias (floats)
    const int SMEM128 = (2 * 128 * 36 + 2 * 32 * 136 + 128) * 4;  // 72192 B
    const int SMEM64  = (2 * 128 * 36 + 2 * 32 * 72  + 64) * 4;   // 55552 B
    cudaFuncSetAttribute(gemm_tc_kernel<128, true, 0, 1, 0>,
                         cudaFuncAttributeMaxDynamicSharedMemorySize, SMEM128);
    cudaFuncSetAttribute(gemm_tc_kernel<128, true, 1, 2, 1>,
                         cudaFuncAttributeMaxDynamicSharedMemorySize, SMEM128);
    cudaFuncSetAttribute(gemm_tc_kernel<64, false, 2, 0, 2>,
                         cudaFuncAttributeMaxDynamicSharedMemorySize, SMEM64);

    const int NB = (N_NODES + 255) / 256;            // 196
    const int AGG_BLOCKS  = (N_NODES * 32 + 255) / 256;
    const int GEMM_BLOCKS = (N_NODES + 127) / 128;   // 391

    // ---- prep (zero counts + tf32 weights + tf32 x) ----
    prep_kernel<<<320, 256>>>(x, Ws0, Wn0, Ws1, Wn1, Ws2, Wn2);

    // ---- CSR build (by dst) ----
    hist_kernel<<<(N_EDGES + 255) / 256, 256>>>(dst);
    reduce_counts_kernel<<<NB, 256>>>();
    scan_partials_kernel<<<1, 256>>>();
    block_scan_kernel<<<NB, 256>>>();
    scatter_kernel<<<(N_EDGES + 255) / 256, 256>>>(src, dst);

    // ---- layer 0: x -> g_h1 ----
    aggregate_kernel<0><<<AGG_BLOCKS, 256>>>(x);
    gemm_tc_kernel<128, true, 0, 1, 0><<<GEMM_BLOCKS, 256, SMEM128>>>(b0, nullptr);

    // ---- layer 1: g_h1 -> g_h2 ----
    aggregate_kernel<1><<<AGG_BLOCKS, 256>>>(nullptr);
    gemm_tc_kernel<128, true, 1, 2, 1><<<GEMM_BLOCKS, 256, SMEM128>>>(b1, nullptr);

    // ---- layer 2: g_h2 -> out ----
    aggregate_kernel<2><<<AGG_BLOCKS, 256>>>(nullptr);
    gemm_tc_kernel<64, false, 2, 0, 2><<<GEMM_BLOCKS, 256, SMEM64>>>(b2, out);
}